// round 8
// baseline (speedup 1.0000x reference)
#include <cuda_runtime.h>
#include <cuda_bf16.h>
#include <cuda_pipeline_primitives.h>

// GraphAttentionLayer: out = elu(softmax(h_j @ a_j + const) @ h_j)
// SINGLE kernel. cp.async ring with QUAD-granular commit groups (2 groups x
// 4 rows = 4KB/warp in flight), 3 blocks/SM (48 warps) for latency hiding.
// Rare-rescale online softmax; last-block-done finalize combines L2-hot.
// h_i . a_i is a constant logit shift -> cancels in softmax -> skipped.

#define D        128
#define NB       444          // 3 * 148 SMs -> one full wave at 3 blocks/SM
#define NT       512          // threads per block
#define WPB      (NT / 32)    // 16 warps
#define NW       (NB * WPB)   // 7104 warps
#define GRP      (NT / D)     // 4 finalize groups over the dim axis
#define ROWB     512          // bytes per row (128 f32)
#define RING_B   (WPB * 8 * ROWB)   // 8 row-slots per warp = 64KB/block

__device__ float g_m[NB];
__device__ float g_s[NB];
__device__ float g_acc[NB * D];
__device__ unsigned int g_count;

__device__ __forceinline__ float dot4(const float4& h, const float4& a) {
    return h.x * a.x + h.y * a.y + h.z * a.z + h.w * a.w;
}

// d is warp-uniform. Rescale only when a new max appears (rare).
__device__ __forceinline__ void upd(float d, const float4& h,
                                    float& m, float& s, float4& acc) {
    if (d > m) {
        float c = __expf(m - d);
        s = s * c + 1.0f;
        acc.x = acc.x * c + h.x;
        acc.y = acc.y * c + h.y;
        acc.z = acc.z * c + h.z;
        acc.w = acc.w * c + h.w;
        m = d;
    } else {
        float w = __expf(d - m);
        s += w;
        acc.x += w * h.x;
        acc.y += w * h.y;
        acc.z += w * h.z;
        acc.w += w * h.w;
    }
}

__device__ __forceinline__ void reduce4(float& d0, float& d1, float& d2, float& d3) {
    #pragma unroll
    for (int o = 16; o > 0; o >>= 1) {
        d0 += __shfl_xor_sync(0xffffffffu, d0, o);
        d1 += __shfl_xor_sync(0xffffffffu, d1, o);
        d2 += __shfl_xor_sync(0xffffffffu, d2, o);
        d3 += __shfl_xor_sync(0xffffffffu, d3, o);
    }
}

extern __shared__ __align__(16) unsigned char sraw[];   // RING_B bytes

__global__ __launch_bounds__(NT, 3)
void gat_fused(const float* __restrict__ hj, const float* __restrict__ a,
               int nrows, float* __restrict__ out) {
    const int warp = threadIdx.x >> 5;
    const int lane = threadIdx.x & 31;

    unsigned char* ring = sraw + warp * (8 * ROWB) + lane * 16;

    const float4 aj = *reinterpret_cast<const float4*>(a + D + lane * 4);

    const int gw    = blockIdx.x * WPB + warp;
    const int chunk = (nrows + NW - 1) / NW;
    int r0 = gw * chunk;
    int r1 = r0 + chunk;
    if (r0 > nrows) r0 = nrows;
    if (r1 > nrows) r1 = nrows;
    const int n = (r1 > r0) ? (r1 - r0) : 0;

    const float* base = hj + (size_t)r0 * D + lane * 4;

    const int nq = n >> 2;                 // full quads

    // Prologue: fill up to 2 quad-groups (always 2 commits for fixed depth)
    #pragma unroll
    for (int g = 0; g < 2; ++g) {
        if (g < nq) {
            const float* p = base + (size_t)(4 * g) * D;
            #pragma unroll
            for (int j = 0; j < 4; ++j)
                __pipeline_memcpy_async(ring + (4 * g + j) * ROWB, p + j * D, 16);
        }
        __pipeline_commit();
    }

    float  m = -1e30f;
    float  s = 0.0f;
    float4 acc = make_float4(0.f, 0.f, 0.f, 0.f);

    for (int q = 0; q < nq; ++q) {
        __pipeline_wait_prior(1);          // oldest quad-group ready
        unsigned char* slot = ring + (q & 1) * (4 * ROWB);
        float4 h0 = *reinterpret_cast<const float4*>(slot);
        float4 h1 = *reinterpret_cast<const float4*>(slot + ROWB);
        float4 h2 = *reinterpret_cast<const float4*>(slot + 2 * ROWB);
        float4 h3 = *reinterpret_cast<const float4*>(slot + 3 * ROWB);

        // refill this group with quad q+2 (lands long after the LDS above)
        if (q + 2 < nq) {
            const float* p = base + (size_t)(4 * (q + 2)) * D;
            #pragma unroll
            for (int j = 0; j < 4; ++j)
                __pipeline_memcpy_async(slot + j * ROWB, p + j * D, 16);
        }
        __pipeline_commit();

        float d0 = dot4(h0, aj);
        float d1 = dot4(h1, aj);
        float d2 = dot4(h2, aj);
        float d3 = dot4(h3, aj);
        reduce4(d0, d1, d2, d3);

        upd(d0, h0, m, s, acc);
        upd(d1, h1, m, s, acc);
        upd(d2, h2, m, s, acc);
        upd(d3, h3, m, s, acc);
    }
    __pipeline_wait_prior(0);

    // Leftover rows (<4) straight from gmem
    for (int r = nq * 4; r < n; ++r) {
        float4 h = __ldcg(reinterpret_cast<const float4*>(base + (size_t)r * D));
        float d = dot4(h, aj);
        #pragma unroll
        for (int o = 16; o > 0; o >>= 1)
            d += __shfl_xor_sync(0xffffffffu, d, o);
        upd(d, h, m, s, acc);
    }

    // ---- Block combine (aliased into sraw; ring contents dead) ----
    __syncthreads();
    float* sm_acc  = reinterpret_cast<float*>(sraw);                // [WPB][D] 8KB
    float* sm_m    = reinterpret_cast<float*>(sraw + 8192);         // [WPB]
    float* sm_s    = reinterpret_cast<float*>(sraw + 8256);         // [WPB]
    float* red     = reinterpret_cast<float*>(sraw + 8320);         // [WPB]
    float* sm_MS   = reinterpret_cast<float*>(sraw + 8384);         // M, S
    float* sm_c    = reinterpret_cast<float*>(sraw + 8448);         // [NB]
    float* sm_part = reinterpret_cast<float*>(sraw + 8448 + 1792);  // [GRP][D]

    if (lane == 0) { sm_m[warp] = m; sm_s[warp] = s; }
    *reinterpret_cast<float4*>(&sm_acc[warp * D + lane * 4]) = acc;
    __syncthreads();

    if (threadIdx.x < D) {
        const int d = threadIdx.x;
        float M = -1e30f;
        #pragma unroll
        for (int w = 0; w < WPB; ++w) M = fmaxf(M, sm_m[w]);

        float st = 0.f, ad = 0.f;
        #pragma unroll
        for (int w = 0; w < WPB; ++w) {
            float c = __expf(sm_m[w] - M);
            st += sm_s[w] * c;
            ad += sm_acc[w * D + d] * c;
        }
        g_acc[blockIdx.x * D + d] = ad;
        if (d == 0) { g_m[blockIdx.x] = M; g_s[blockIdx.x] = st; }
    }

    // ---- Last-block-done finalize (partials L2-hot) ----
    __threadfence();
    __shared__ bool isLast;
    if (threadIdx.x == 0) {
        unsigned v = atomicAdd(&g_count, 1u);
        isLast = (v == NB - 1);
    }
    __syncthreads();
    if (!isLast) return;
    if (threadIdx.x == 0) g_count = 0;     // reset for graph replay

    const int t = threadIdx.x;

    float mreg = (t < NB) ? __ldcg(&g_m[t]) : -1e30f;
    float mv = mreg;
    #pragma unroll
    for (int o = 16; o > 0; o >>= 1) mv = fmaxf(mv, __shfl_xor_sync(0xffffffffu, mv, o));
    if (lane == 0) red[warp] = mv;
    __syncthreads();
    if (t == 0) {
        float v = red[0];
        #pragma unroll
        for (int w = 1; w < WPB; ++w) v = fmaxf(v, red[w]);
        sm_MS[0] = v;
    }
    __syncthreads();
    const float M = sm_MS[0];

    float sv = 0.f;
    if (t < NB) {
        float c = __expf(mreg - M);
        sm_c[t] = c;
        sv = __ldcg(&g_s[t]) * c;
    }
    #pragma unroll
    for (int o = 16; o > 0; o >>= 1) sv += __shfl_xor_sync(0xffffffffu, sv, o);
    __syncthreads();
    if (lane == 0) red[warp] = sv;
    __syncthreads();
    if (t == 0) {
        float v = 0.f;
        #pragma unroll
        for (int w = 0; w < WPB; ++w) v += red[w];
        sm_MS[1] = v;
    }
    __syncthreads();

    const int d   = t & (D - 1);
    const int grp = t >> 7;
    float ad = 0.f;
    for (int b = grp; b < NB; b += GRP)
        ad += __ldcg(&g_acc[b * D + d]) * sm_c[b];
    sm_part[grp * D + d] = ad;
    __syncthreads();

    if (t < D) {
        float total = 0.f;
        #pragma unroll
        for (int g = 0; g < GRP; ++g) total += sm_part[g * D + t];
        float h = total / sm_MS[1];
        out[t] = (h > 0.f) ? h : expm1f(h);    // ELU, alpha = 1
    }
}

extern "C" void kernel_launch(void* const* d_in, const int* in_sizes, int n_in,
                              void* d_out, int out_size) {
    // inputs: [0] h_i (unused: constant logit shift cancels in softmax),
    //         [1] h_j [200000,128] f32, [2] a [256,1] f32
    const float* hj = (const float*)d_in[1];
    const float* a  = (const float*)d_in[2];
    const int nrows = in_sizes[1] / D;

    cudaFuncSetAttribute(gat_fused, cudaFuncAttributeMaxDynamicSharedMemorySize, RING_B);
    gat_fused<<<NB, NT, RING_B>>>(hj, a, nrows, (float*)d_out);
}

// round 9
// speedup vs baseline: 1.1633x; 1.1633x over previous
#include <cuda_runtime.h>
#include <cuda_bf16.h>

// GraphAttentionLayer: out = elu(softmax(h_j @ a_j + const) @ h_j)
// SINGLE kernel, minimal-register plain-LDG loop at 3 blocks/SM (48 warps):
// warps parked on outstanding loads ARE the bandwidth resource.
// Rare-rescale online softmax (one branch per 4-row quad).
// Last-block-done finalize combines partials L2-hot.
// h_i . a_i is a constant logit shift -> cancels in softmax -> skipped.

#define D        128
#define NB       444          // 3 * 148 SMs -> one wave at 3 blocks/SM
#define NT       512
#define WPB      (NT / 32)    // 16 warps
#define NW       (NB * WPB)   // 7104 warps
#define GRP      (NT / D)     // 4 finalize groups

__device__ float g_m[NB];
__device__ float g_s[NB];
__device__ float g_acc[NB * D];
__device__ unsigned int g_count;

__device__ __forceinline__ float dot4(const float4& h, const float4& a) {
    return h.x * a.x + h.y * a.y + h.z * a.z + h.w * a.w;
}

__global__ __launch_bounds__(NT, 3)
void gat_fused(const float* __restrict__ hj, const float* __restrict__ a,
               int nrows, float* __restrict__ out) {
    const int warp = threadIdx.x >> 5;
    const int lane = threadIdx.x & 31;

    const float4 aj = *reinterpret_cast<const float4*>(a + D + lane * 4);

    const int gw    = blockIdx.x * WPB + warp;
    const int chunk = (nrows + NW - 1) / NW;
    int r0 = gw * chunk;
    int r1 = r0 + chunk;
    if (r0 > nrows) r0 = nrows;
    if (r1 > nrows) r1 = nrows;
    const int n = (r1 > r0) ? (r1 - r0) : 0;

    float  m = -1e30f;
    float  s = 0.0f;
    float4 acc = make_float4(0.f, 0.f, 0.f, 0.f);

    const float4* p = reinterpret_cast<const float4*>(hj + (size_t)r0 * D + lane * 4);

    int i = 0;
    for (; i + 4 <= n; i += 4, p += D) {       // p steps 4 rows (4*128/4 float4s)
        // 4 independent 512B warp loads, issued back-to-back (L1-bypass)
        float4 h0 = __ldcg(p);
        float4 h1 = __ldcg(p + (D / 4));
        float4 h2 = __ldcg(p + (D / 2));
        float4 h3 = __ldcg(p + (3 * D / 4));

        float d0 = dot4(h0, aj);
        float d1 = dot4(h1, aj);
        float d2 = dot4(h2, aj);
        float d3 = dot4(h3, aj);

        #pragma unroll
        for (int o = 16; o > 0; o >>= 1) {     // 4 interleaved reduce chains
            d0 += __shfl_xor_sync(0xffffffffu, d0, o);
            d1 += __shfl_xor_sync(0xffffffffu, d1, o);
            d2 += __shfl_xor_sync(0xffffffffu, d2, o);
            d3 += __shfl_xor_sync(0xffffffffu, d3, o);
        }

        float gm = fmaxf(fmaxf(d0, d1), fmaxf(d2, d3));
        if (gm > m) {                           // rare (warp-uniform)
            float c = __expf(m - gm);
            s *= c;
            acc.x *= c; acc.y *= c; acc.z *= c; acc.w *= c;
            m = gm;
        }
        // common path: 4 independent MUFUs, short FMA chains
        float w0 = __expf(d0 - m);
        float w1 = __expf(d1 - m);
        float w2 = __expf(d2 - m);
        float w3 = __expf(d3 - m);
        s += (w0 + w1) + (w2 + w3);
        acc.x += w0 * h0.x + w1 * h1.x + w2 * h2.x + w3 * h3.x;
        acc.y += w0 * h0.y + w1 * h1.y + w2 * h2.y + w3 * h3.y;
        acc.z += w0 * h0.z + w1 * h1.z + w2 * h2.z + w3 * h3.z;
        acc.w += w0 * h0.w + w1 * h1.w + w2 * h2.w + w3 * h3.w;
    }
    for (; i < n; ++i, p += (D / 4)) {          // tail rows
        float4 h = __ldcg(p);
        float d = dot4(h, aj);
        #pragma unroll
        for (int o = 16; o > 0; o >>= 1)
            d += __shfl_xor_sync(0xffffffffu, d, o);
        if (d > m) {
            float c = __expf(m - d);
            s = s * c + 1.0f;
            acc.x = acc.x * c + h.x;
            acc.y = acc.y * c + h.y;
            acc.z = acc.z * c + h.z;
            acc.w = acc.w * c + h.w;
            m = d;
        } else {
            float w = __expf(d - m);
            s += w;
            acc.x += w * h.x; acc.y += w * h.y;
            acc.z += w * h.z; acc.w += w * h.w;
        }
    }

    // ---- Block combine in shared memory ----
    __shared__ float sm_m[WPB];
    __shared__ float sm_s[WPB];
    __shared__ __align__(16) float sm_acc[WPB][D];

    if (lane == 0) { sm_m[warp] = m; sm_s[warp] = s; }
    *reinterpret_cast<float4*>(&sm_acc[warp][lane * 4]) = acc;
    __syncthreads();

    if (threadIdx.x < D) {
        const int d = threadIdx.x;
        float M = -1e30f;
        #pragma unroll
        for (int w = 0; w < WPB; ++w) M = fmaxf(M, sm_m[w]);

        float st = 0.f, ad = 0.f;
        #pragma unroll
        for (int w = 0; w < WPB; ++w) {
            float c = __expf(sm_m[w] - M);
            st += sm_s[w] * c;
            ad += sm_acc[w][d] * c;
        }
        g_acc[blockIdx.x * D + d] = ad;
        if (d == 0) { g_m[blockIdx.x] = M; g_s[blockIdx.x] = st; }
    }

    // ---- Last-block-done finalize (partials L2-hot) ----
    __threadfence();
    __shared__ bool isLast;
    if (threadIdx.x == 0) {
        unsigned v = atomicAdd(&g_count, 1u);
        isLast = (v == NB - 1);
    }
    __syncthreads();
    if (!isLast) return;
    if (threadIdx.x == 0) g_count = 0;     // reset for graph replay

    const int t = threadIdx.x;
    __shared__ float red[WPB];
    __shared__ float sm_M, sm_S;
    __shared__ float sm_c[NB];
    __shared__ __align__(16) float sm_part[GRP][D];

    float mreg = (t < NB) ? __ldcg(&g_m[t]) : -1e30f;
    float mv = mreg;
    #pragma unroll
    for (int o = 16; o > 0; o >>= 1) mv = fmaxf(mv, __shfl_xor_sync(0xffffffffu, mv, o));
    if (lane == 0) red[warp] = mv;
    __syncthreads();
    if (t == 0) {
        float v = red[0];
        #pragma unroll
        for (int w = 1; w < WPB; ++w) v = fmaxf(v, red[w]);
        sm_M = v;
    }
    __syncthreads();
    const float M = sm_M;

    float sv = 0.f;
    if (t < NB) {
        float c = __expf(mreg - M);
        sm_c[t] = c;
        sv = __ldcg(&g_s[t]) * c;
    }
    #pragma unroll
    for (int o = 16; o > 0; o >>= 1) sv += __shfl_xor_sync(0xffffffffu, sv, o);
    __syncthreads();
    if (lane == 0) red[warp] = sv;
    __syncthreads();
    if (t == 0) {
        float v = 0.f;
        #pragma unroll
        for (int w = 0; w < WPB; ++w) v += red[w];
        sm_S = v;
    }
    __syncthreads();

    const int d   = t & (D - 1);
    const int grp = t >> 7;
    float ad = 0.f;
    for (int b = grp; b < NB; b += GRP)
        ad += __ldcg(&g_acc[b * D + d]) * sm_c[b];
    sm_part[grp][d] = ad;
    __syncthreads();

    if (t < D) {
        float total = 0.f;
        #pragma unroll
        for (int g = 0; g < GRP; ++g) total += sm_part[g][t];
        float h = total / sm_S;
        out[t] = (h > 0.f) ? h : expm1f(h);    // ELU, alpha = 1
    }
}

extern "C" void kernel_launch(void* const* d_in, const int* in_sizes, int n_in,
                              void* d_out, int out_size) {
    // inputs: [0] h_i (unused: constant logit shift cancels in softmax),
    //         [1] h_j [200000,128] f32, [2] a [256,1] f32
    const float* hj = (const float*)d_in[1];
    const float* a  = (const float*)d_in[2];
    const int nrows = in_sizes[1] / D;

    gat_fused<<<NB, NT>>>(hj, a, nrows, (float*)d_out);
}